// round 4
// baseline (speedup 1.0000x reference)
#include <cuda_runtime.h>
#include <cstdint>

// Problem constants
#define Bq 2
#define Tq 2048
#define Dq 1024
#define VDq 2048
#define FFq 2752
#define Hq 16
#define DKq 64
#define DVq 128
#define Mq (Bq*Tq)   // 4096 rows

// ---------------- scratch (device globals; no allocation allowed) ----------
__device__ float g_h [Mq*(size_t)Dq];
__device__ float g_qp[Mq*(size_t)Dq];
__device__ float g_kp[Mq*(size_t)Dq];
__device__ float g_vp[Mq*(size_t)VDq];
__device__ float g_q [Mq*(size_t)Dq];
__device__ float g_k [Mq*(size_t)Dq];
__device__ float g_v [Mq*(size_t)VDq];
__device__ float g_gt[Mq*(size_t)VDq];
__device__ float g_bt[Mq*(size_t)Hq];
__device__ float g_gd[Mq*(size_t)Hq];
__device__ float g_o [Mq*(size_t)VDq];
__device__ float g_x [Mq*(size_t)Dq];
__device__ float g_h2[Mq*(size_t)Dq];
__device__ float g_gb[Mq*(size_t)FFq];
__device__ float g_ub[Mq*(size_t)FFq];

// ---------------- helpers ---------------------------------------------------
__device__ __forceinline__ float siluf(float x) {
    return x / (1.0f + __expf(-x));
}

__device__ __forceinline__ unsigned long long ffma2(unsigned long long a,
                                                    unsigned long long b,
                                                    unsigned long long c) {
    unsigned long long d;
    asm("fma.rn.f32x2 %0, %1, %2, %3;" : "=l"(d) : "l"(a), "l"(b), "l"(c));
    return d;
}
__device__ __forceinline__ unsigned long long dup2(float x) {
    unsigned long long r;
    asm("mov.b64 %0, {%1, %1};" : "=l"(r) : "f"(x));
    return r;
}

// ---------------- RMSNorm over D=1024, one block per row --------------------
__global__ void rmsnorm_kernel(const float* __restrict__ x,
                               const float* __restrict__ w,
                               float* __restrict__ out) {
    int row = blockIdx.x;
    const float4* xr = (const float4*)(x + (size_t)row * Dq);
    float4 v = xr[threadIdx.x];
    float ss = v.x*v.x + v.y*v.y + v.z*v.z + v.w*v.w;
    #pragma unroll
    for (int o = 16; o; o >>= 1) ss += __shfl_xor_sync(0xffffffffu, ss, o);
    __shared__ float red[8];
    int wid = threadIdx.x >> 5, lane = threadIdx.x & 31;
    if (lane == 0) red[wid] = ss;
    __syncthreads();
    float tot = red[0]+red[1]+red[2]+red[3]+red[4]+red[5]+red[6]+red[7];
    float r = rsqrtf(tot * (1.0f / Dq) + 1e-6f);
    float4 wv = ((const float4*)w)[threadIdx.x];
    float4 ov = make_float4(v.x*r*wv.x, v.y*r*wv.y, v.z*r*wv.z, v.w*r*wv.w);
    ((float4*)(out + (size_t)row * Dq))[threadIdx.x] = ov;
}

// ---------------- causal depthwise conv (K=4) + silu -------------------------
__global__ void conv_silu_kernel(const float* __restrict__ in,
                                 const float* __restrict__ w,
                                 float* __restrict__ out, int C) {
    size_t idx = (size_t)blockIdx.x * blockDim.x + threadIdx.x;
    size_t total = (size_t)Mq * C;
    if (idx >= total) return;
    int c = (int)(idx % C);
    size_t bt = idx / C;
    int t = (int)(bt % Tq);
    float4 wv = ((const float4*)w)[c];               // w[c,0..3]
    float acc = wv.w * in[idx];                       // i=3 -> x[t]
    if (t >= 1) acc += wv.z * in[idx - (size_t)C];
    if (t >= 2) acc += wv.y * in[idx - 2*(size_t)C];
    if (t >= 3) acc += wv.x * in[idx - 3*(size_t)C];
    out[idx] = siluf(acc);
}

// ---------------- L2 norm over DK=64 vectors (in place), warp per vector ----
__global__ void l2norm_kernel(float* __restrict__ p) {
    int vec = blockIdx.x * 8 + (threadIdx.x >> 5);
    int lane = threadIdx.x & 31;
    float2* vp = (float2*)(p + (size_t)vec * DKq);
    float2 v = vp[lane];
    float ss = v.x*v.x + v.y*v.y;
    #pragma unroll
    for (int o = 16; o; o >>= 1) ss += __shfl_xor_sync(0xffffffffu, ss, o);
    float r = rsqrtf(ss + 1e-6f);
    vp[lane] = make_float2(v.x * r, v.y * r);
}

// ---------------- beta / g decay (skinny N=16 projections) -------------------
__global__ void ba_kernel(const float* __restrict__ h,
                          const float* __restrict__ b_w,
                          const float* __restrict__ a_w,
                          const float* __restrict__ A_log,
                          const float* __restrict__ dt_bias,
                          float* __restrict__ beta,
                          float* __restrict__ gd) {
    int row = blockIdx.x * 4 + (threadIdx.x >> 5);
    int lane = threadIdx.x & 31;
    int c = lane & 15;
    const float* W = (lane < 16) ? b_w : a_w;
    const float* hr = h + (size_t)row * Dq;
    float a0 = 0.f, a1 = 0.f, a2 = 0.f, a3 = 0.f;
    for (int kk = 0; kk < Dq; kk += 4) {
        a0 += hr[kk+0] * W[(kk+0)*Hq + c];
        a1 += hr[kk+1] * W[(kk+1)*Hq + c];
        a2 += hr[kk+2] * W[(kk+2)*Hq + c];
        a3 += hr[kk+3] * W[(kk+3)*Hq + c];
    }
    float acc = (a0 + a1) + (a2 + a3);
    if (lane < 16) {
        beta[(size_t)row * Hq + c] = 1.0f / (1.0f + __expf(-acc));
    } else {
        float xv = acc + dt_bias[c];
        float sp = fmaxf(xv, 0.f) + log1pf(__expf(-fabsf(xv)));  // stable softplus
        gd[(size_t)row * Hq + c] = -__expf(A_log[c]) * sp;
    }
}

// ---------------- gated delta-rule scan --------------------------------------
// grid = B*H*2 CTAs (each CTA owns half of DV); 256 threads.
// thread: col = half*64 + (tid>>2); owns 16 state rows (sub = tid&3).
__global__ void __launch_bounds__(256)
scan_kernel(const float* __restrict__ q, const float* __restrict__ k,
            const float* __restrict__ v, const float* __restrict__ gd,
            const float* __restrict__ bt, float* __restrict__ o) {
    int half = blockIdx.x & 1;
    int bh = blockIdx.x >> 1;
    int b = bh >> 4, h = bh & 15;
    int tid = threadIdx.x;
    int colL = tid >> 2;
    int sub = tid & 3;
    int col = half * 64 + colL;

    __shared__ float ks[2][64];
    __shared__ float qs[2][64];
    __shared__ float sc[2][2];   // [buf][0]=g, [buf][1]=beta

    size_t baseQK = ((size_t)(b * Tq) * Hq + h) * DKq;      // + t*Hq*DKq
    size_t baseV  = ((size_t)(b * Tq) * Hq + h) * DVq + col; // + t*Hq*DVq
    size_t baseS  = (size_t)(b * Tq) * Hq + h;               // + t*Hq

    float S[16];
    #pragma unroll
    for (int j = 0; j < 16; j++) S[j] = 0.f;

    bool isK = (tid < 64);
    bool isQ = (tid >= 64 && tid < 128);
    bool isS = (tid == 128 || tid == 129);
    int li = tid & 63;
    int si = tid - 128;

    // depth-2 prefetch registers
    float rk0 = 0.f, rk1 = 0.f, rq0 = 0.f, rq1 = 0.f, rs0 = 0.f, rs1 = 0.f;
    float rv0, rv1;

    // prologue: smem buf0 <- t=0, regs <- t=1, t=2
    if (isK) {
        ks[0][li] = k[baseQK + li];
        rk0 = k[baseQK + (size_t)1 * Hq * DKq + li];
        rk1 = k[baseQK + (size_t)2 * Hq * DKq + li];
    }
    if (isQ) {
        qs[0][li] = q[baseQK + li] * 0.125f;
        rq0 = q[baseQK + (size_t)1 * Hq * DKq + li] * 0.125f;
        rq1 = q[baseQK + (size_t)2 * Hq * DKq + li] * 0.125f;
    }
    if (isS) {
        const float* sp = (si == 0) ? gd : bt;
        sc[0][si] = sp[baseS];
        rs0 = sp[baseS + (size_t)1 * Hq];
        rs1 = sp[baseS + (size_t)2 * Hq];
    }
    rv0 = v[baseV];
    rv1 = v[baseV + (size_t)1 * Hq * DVq];
    __syncthreads();

    for (int t = 0; t < Tq; t++) {
        int cur = t & 1, nxt = cur ^ 1;
        // stage t+1 into other buffer; refill depth-2 regs with t+3
        if (t + 1 < Tq) {
            if (isK) {
                ks[nxt][li] = rk0; rk0 = rk1;
                rk1 = (t + 3 < Tq) ? k[baseQK + (size_t)(t + 3) * Hq * DKq + li] : 0.f;
            }
            if (isQ) {
                qs[nxt][li] = rq0; rq0 = rq1;
                rq1 = (t + 3 < Tq) ? q[baseQK + (size_t)(t + 3) * Hq * DKq + li] * 0.125f : 0.f;
            }
            if (isS) {
                sc[nxt][si] = rs0; rs0 = rs1;
                if (t + 3 < Tq) {
                    const float* sp = (si == 0) ? gd : bt;
                    rs1 = sp[baseS + (size_t)(t + 3) * Hq];
                } else rs1 = 0.f;
            }
        }
        float vt = rv0; rv0 = rv1;
        rv1 = (t + 2 < Tq) ? v[baseV + (size_t)(t + 2) * Hq * DVq] : 0.f;

        float gde = sc[cur][0], bet = sc[cur][1];
        float decay = __expf(gde);
        const float* kk = &ks[cur][sub * 16];
        const float* qq = &qs[cur][sub * 16];

        float vp0 = 0.f, vp1 = 0.f;
        #pragma unroll
        for (int j = 0; j < 16; j += 2) {
            S[j]   *= decay; vp0 += kk[j]   * S[j];
            S[j+1] *= decay; vp1 += kk[j+1] * S[j+1];
        }
        float vp = vp0 + vp1;
        vp += __shfl_xor_sync(0xffffffffu, vp, 1);
        vp += __shfl_xor_sync(0xffffffffu, vp, 2);
        float u = bet * (vt - vp);

        float ot0 = 0.f, ot1 = 0.f;
        #pragma unroll
        for (int j = 0; j < 16; j += 2) {
            S[j]   += kk[j]   * u; ot0 += qq[j]   * S[j];
            S[j+1] += kk[j+1] * u; ot1 += qq[j+1] * S[j+1];
        }
        float ot = ot0 + ot1;
        ot += __shfl_xor_sync(0xffffffffu, ot, 1);
        ot += __shfl_xor_sync(0xffffffffu, ot, 2);
        if (sub == 0) o[baseV + (size_t)t * Hq * DVq] = ot;
        __syncthreads();
    }
}

// ---------------- gated per-head RMSNorm: o = rms(o)*w * silu(gate) ---------
__global__ void gated_rmsnorm_kernel(float* __restrict__ o,
                                     const float* __restrict__ w,
                                     const float* __restrict__ gate) {
    int vec = blockIdx.x * 8 + (threadIdx.x >> 5);
    int lane = threadIdx.x & 31;
    float4* op = (float4*)(o + (size_t)vec * DVq);
    const float4* gp = (const float4*)(gate + (size_t)vec * DVq);
    float4 v = op[lane];
    float ss = v.x*v.x + v.y*v.y + v.z*v.z + v.w*v.w;
    #pragma unroll
    for (int off = 16; off; off >>= 1) ss += __shfl_xor_sync(0xffffffffu, ss, off);
    float r = rsqrtf(ss * (1.0f / DVq) + 1e-6f);
    float4 wv = ((const float4*)w)[lane];
    float4 g = gp[lane];
    float4 out;
    out.x = v.x * r * wv.x * siluf(g.x);
    out.y = v.y * r * wv.y * siluf(g.y);
    out.z = v.z * r * wv.z * siluf(g.z);
    out.w = v.w * r * wv.w * siluf(g.w);
    op[lane] = out;
}

// ---------------- SwiGLU activation: gb = silu(gb) * ub ---------------------
__global__ void act_kernel(float* __restrict__ gb, const float* __restrict__ ub) {
    size_t i = (size_t)blockIdx.x * 256 + threadIdx.x;
    if (i >= (size_t)Mq * FFq / 4) return;
    float4 g = ((float4*)gb)[i];
    float4 u = ((const float4*)ub)[i];
    g.x = siluf(g.x) * u.x;
    g.y = siluf(g.y) * u.y;
    g.z = siluf(g.z) * u.z;
    g.w = siluf(g.w) * u.w;
    ((float4*)gb)[i] = g;
}

// ---------------- fp32 GEMM with packed f32x2 FMA ---------------------------
// C[M,N] = A[M,K] @ B[K,N] (+ R), row-major. M=4096, K%16==0, N%4==0.
// 128x128 tile, BK=16, 256 threads, 8x8 per thread, double-buffered smem.
__global__ void __launch_bounds__(256)
gemm_kernel(const float* __restrict__ A, const float* __restrict__ B,
            const float* __restrict__ R, float* __restrict__ C,
            int N, int K, int addR) {
    __shared__ float As[2][16][128];
    __shared__ float Bs[2][16][128];
    const int tid = threadIdx.x;
    const int bm = blockIdx.y * 128;
    const int bn = blockIdx.x * 128;

    const int arow = tid >> 2;          // 0..63 (+64)
    const int acol = (tid & 3) << 2;    // 0,4,8,12
    const int brow = tid >> 5;          // 0..7 (+8)
    const int bcol = (tid & 31) << 2;   // 0..124
    const int tm = (tid >> 4) << 3;
    const int tn = (tid & 15) << 3;

    unsigned long long acc[8][4];
    #pragma unroll
    for (int i = 0; i < 8; i++)
        #pragma unroll
        for (int j = 0; j < 4; j++) acc[i][j] = 0ull;

    auto loadTiles = [&](int buf, int k0) {
        #pragma unroll
        for (int i = 0; i < 2; i++) {
            int r = arow + i * 64;
            float4 va = *(const float4*)(A + (size_t)(bm + r) * K + (k0 + acol));
            As[buf][acol + 0][r] = va.x;
            As[buf][acol + 1][r] = va.y;
            As[buf][acol + 2][r] = va.z;
            As[buf][acol + 3][r] = va.w;
        }
        #pragma unroll
        for (int i = 0; i < 2; i++) {
            int r = brow + i * 8;
            int colg = bn + bcol;
            float4 vb = (colg < N)
                      ? *(const float4*)(B + (size_t)(k0 + r) * N + colg)
                      : make_float4(0.f, 0.f, 0.f, 0.f);
            *(float4*)&Bs[buf][r][bcol] = vb;
        }
    };

    int nk = K >> 4;
    loadTiles(0, 0);
    __syncthreads();
    for (int kt = 0; kt < nk; kt++) {
        int buf = kt & 1;
        if (kt + 1 < nk) loadTiles(buf ^ 1, (kt + 1) << 4);
        #pragma unroll
        for (int k = 0; k < 16; k++) {
            unsigned long long bfr[4];
            const unsigned long long* bp =
                (const unsigned long long*)&Bs[buf][k][tn];
            #pragma unroll
            for (int j = 0; j < 4; j++) bfr[j] = bp[j];
            float4 a0 = *(const float4*)&As[buf][k][tm];
            float4 a1 = *(const float4*)&As[buf][k][tm + 4];
            unsigned long long ad[8];
            ad[0] = dup2(a0.x); ad[1] = dup2(a0.y);
            ad[2] = dup2(a0.z); ad[3] = dup2(a0.w);
            ad[4] = dup2(a1.x); ad[5] = dup2(a1.y);
            ad[6] = dup2(a1.z); ad[7] = dup2(a1.w);
            #pragma unroll
            for (int i = 0; i < 8; i++)
                #pragma unroll
                for (int j = 0; j < 4; j++)
                    acc[i][j] = ffma2(ad[i], bfr[j], acc[i][j]);
        }
        __syncthreads();
    }

    #pragma unroll
    for (int i = 0; i < 8; i++) {
        int row = bm + tm + i;
        #pragma unroll
        for (int j = 0; j < 4; j += 2) {
            int colg = bn + tn + j * 2;
            if (colg < N) {
                float4 ov;
                asm("mov.b64 {%0,%1}, %2;" : "=f"(ov.x), "=f"(ov.y) : "l"(acc[i][j]));
                asm("mov.b64 {%0,%1}, %2;" : "=f"(ov.z), "=f"(ov.w) : "l"(acc[i][j+1]));
                if (addR) {
                    float4 rv = *(const float4*)(R + (size_t)row * N + colg);
                    ov.x += rv.x; ov.y += rv.y; ov.z += rv.z; ov.w += rv.w;
                }
                *(float4*)(C + (size_t)row * N + colg) = ov;
            }
        }
    }
}

// ---------------- host orchestration ----------------------------------------
static inline void launch_gemm(const float* A, const float* B, const float* R,
                               float* C, int N, int K, int addR) {
    dim3 grid((N + 127) / 128, Mq / 128);
    gemm_kernel<<<grid, 256>>>(A, B, R, C, N, K, addR);
}

extern "C" void kernel_launch(void* const* d_in, const int* in_sizes, int n_in,
                              void* d_out, int out_size) {
    const float* hidden     = (const float*)d_in[0];
    const float* norm_w     = (const float*)d_in[1];
    const float* q_w        = (const float*)d_in[2];
    const float* k_w        = (const float*)d_in[3];
    const float* v_w        = (const float*)d_in[4];
    const float* b_w        = (const float*)d_in[5];
    const float* a_w        = (const float*)d_in[6];
    const float* A_log      = (const float*)d_in[7];
    const float* dt_bias    = (const float*)d_in[8];
    const float* conv_q_w   = (const float*)d_in[9];
    const float* conv_k_w   = (const float*)d_in[10];
    const float* conv_v_w   = (const float*)d_in[11];
    const float* g_w        = (const float*)d_in[12];
    const float* o_norm_w   = (const float*)d_in[13];
    const float* o_w        = (const float*)d_in[14];
    const float* post_norm_w= (const float*)d_in[15];
    const float* gate_w     = (const float*)d_in[16];
    const float* up_w       = (const float*)d_in[17];
    const float* down_w     = (const float*)d_in[18];
    float* out = (float*)d_out;

    float *p_h, *p_qp, *p_kp, *p_vp, *p_q, *p_k, *p_v, *p_gt, *p_bt, *p_gd,
          *p_o, *p_x, *p_h2, *p_gb, *p_ub;
    cudaGetSymbolAddress((void**)&p_h,  g_h);
    cudaGetSymbolAddress((void**)&p_qp, g_qp);
    cudaGetSymbolAddress((void**)&p_kp, g_kp);
    cudaGetSymbolAddress((void**)&p_vp, g_vp);
    cudaGetSymbolAddress((void**)&p_q,  g_q);
    cudaGetSymbolAddress((void**)&p_k,  g_k);
    cudaGetSymbolAddress((void**)&p_v,  g_v);
    cudaGetSymbolAddress((void**)&p_gt, g_gt);
    cudaGetSymbolAddress((void**)&p_bt, g_bt);
    cudaGetSymbolAddress((void**)&p_gd, g_gd);
    cudaGetSymbolAddress((void**)&p_o,  g_o);
    cudaGetSymbolAddress((void**)&p_x,  g_x);
    cudaGetSymbolAddress((void**)&p_h2, g_h2);
    cudaGetSymbolAddress((void**)&p_gb, g_gb);
    cudaGetSymbolAddress((void**)&p_ub, g_ub);

    // 1) pre-norm
    rmsnorm_kernel<<<Mq, 256>>>(hidden, norm_w, p_h);

    // 2) projections
    launch_gemm(p_h, q_w, nullptr, p_qp, Dq,  Dq, 0);
    launch_gemm(p_h, k_w, nullptr, p_kp, Dq,  Dq, 0);
    launch_gemm(p_h, v_w, nullptr, p_vp, VDq, Dq, 0);
    launch_gemm(p_h, g_w, nullptr, p_gt, VDq, Dq, 0);
    ba_kernel<<<Mq / 4, 128>>>(p_h, b_w, a_w, A_log, dt_bias, p_bt, p_gd);

    // 3) causal conv + silu
    conv_silu_kernel<<<(Mq * Dq)  / 256, 256>>>(p_qp, conv_q_w, p_q, Dq);
    conv_silu_kernel<<<(Mq * Dq)  / 256, 256>>>(p_kp, conv_k_w, p_k, Dq);
    conv_silu_kernel<<<(Mq * VDq) / 256, 256>>>(p_vp, conv_v_w, p_v, VDq);

    // 4) l2 norm q, k (in place)
    l2norm_kernel<<<(Mq * Hq) / 8, 256>>>(p_q);
    l2norm_kernel<<<(Mq * Hq) / 8, 256>>>(p_k);

    // 5) gated delta rule scan
    scan_kernel<<<Bq * Hq * 2, 256>>>(p_q, p_k, p_v, p_gd, p_bt, p_o);

    // 6) gated per-head RMSNorm (in place on o)
    gated_rmsnorm_kernel<<<(Mq * Hq) / 8, 256>>>(p_o, o_norm_w, p_gt);

    // 7) output projection + residual -> x
    launch_gemm(p_o, o_w, hidden, p_x, Dq, VDq, 1);

    // 8) post norm
    rmsnorm_kernel<<<Mq, 256>>>(p_x, post_norm_w, p_h2);

    // 9) MLP
    launch_gemm(p_h2, gate_w, nullptr, p_gb, FFq, Dq, 0);
    launch_gemm(p_h2, up_w,   nullptr, p_ub, FFq, Dq, 0);
    act_kernel<<<(int)(((size_t)Mq * FFq / 4 + 255) / 256), 256>>>(p_gb, p_ub);
    launch_gemm(p_gb, down_w, p_x, out, Dq, FFq, 1);
}